// round 14
// baseline (speedup 1.0000x reference)
#include <cuda_runtime.h>
#include <cuda_bf16.h>
#include <cstdint>
#include <math.h>

#define NN 8192
#define DD 512

#define BM 128
#define BN 128
#define BK 64                        // bf16 per chunk = 128 B per row
#define NCHUNKS (DD / BK)            // 8
#define GRID_X (NN / BN)             // 64
#define GRID_Y (NN / BM)             // 64

// dynamic SMEM: 3 stages x (A 16KB + B 16KB), then reduction area
#define STAGE 32768
#define SBOFF 16384
#define SRED  98304                  // 256 floats
#define SMEM_TOTAL (98304 + 1024)

__device__ __nv_bfloat16 g_cnb[(size_t)NN * DD];
__device__ __nv_bfloat16 g_enb[(size_t)NN * DD];
__device__ float g_prow[(size_t)GRID_X * NN];
__device__ float g_pcol[(size_t)GRID_Y * NN];
__device__ float g_diag[NN];

__device__ __forceinline__ uint32_t smem_u32(const void* p) {
    uint32_t a;
    asm("{ .reg .u64 t; cvta.to.shared.u64 t, %1; cvt.u32.u64 %0, t; }"
        : "=r"(a) : "l"(p));
    return a;
}

// ------------- 1. normalize -> bf16: one warp per row ------------------------
__global__ void knorm(const float* __restrict__ in0, const float* __restrict__ in1,
                      __nv_bfloat16* __restrict__ out0, __nv_bfloat16* __restrict__ out1,
                      float* __restrict__ loss_out) {
    if (blockIdx.x == 0 && threadIdx.x == 0) loss_out[0] = 0.0f;
    const int wid = threadIdx.x >> 5, lid = threadIdx.x & 31;
    int gr = blockIdx.x * 8 + wid;                   // [0, 2*NN)
    const float* in = (gr < NN) ? in0 : in1;
    __nv_bfloat16* out = (gr < NN) ? out0 : out1;
    int row = gr & (NN - 1);

    const float4* ip = reinterpret_cast<const float4*>(in + (size_t)row * DD);
    float4 v[4];
    #pragma unroll
    for (int j = 0; j < 4; j++) v[j] = ip[lid + 32 * j];

    float ss = 0.0f;
    #pragma unroll
    for (int j = 0; j < 4; j++)
        ss += v[j].x * v[j].x + v[j].y * v[j].y + v[j].z * v[j].z + v[j].w * v[j].w;
    #pragma unroll
    for (int o = 16; o; o >>= 1) ss += __shfl_xor_sync(0xffffffffu, ss, o);
    float inv = 1.0f / fmaxf(sqrtf(ss), 1e-8f);

    uint2* op = reinterpret_cast<uint2*>(out + (size_t)row * DD);
    #pragma unroll
    for (int j = 0; j < 4; j++) {
        __nv_bfloat162 lo = __floats2bfloat162_rn(v[j].x * inv, v[j].y * inv);
        __nv_bfloat162 hi = __floats2bfloat162_rn(v[j].z * inv, v[j].w * inv);
        uint2 w;
        w.x = *reinterpret_cast<uint32_t*>(&lo);
        w.y = *reinterpret_cast<uint32_t*>(&hi);
        op[lid + 32 * j] = w;
    }
}

// ------------- 2. fused bf16 mma.sync GEMM + exp-sum epilogue ---------------
// 4 warps: warp grid 2(M) x 2(N); warp tile 64x64; frags 4(m16) x 8(n8)
// 3-stage cp.async pipeline, fully unrolled, 1 barrier per chunk
__global__ void __launch_bounds__(128, 2) kmain(const float* __restrict__ tptr) {
    extern __shared__ char smem[];
    const uint32_t smb = smem_u32(smem);
    const int tid = threadIdx.x;
    const int wid = tid >> 5, lid = tid & 31;
    const int wm = wid >> 1, wn = wid & 1;       // 2 x 2 warp grid
    const int bm = blockIdx.y * BM;
    const int bn = blockIdx.x * BN;

    float acc[4][8][4];
    #pragma unroll
    for (int i = 0; i < 4; i++)
        #pragma unroll
        for (int j = 0; j < 8; j++)
            #pragma unroll
            for (int e = 0; e < 4; e++) acc[i][j][e] = 0.0f;

    auto load_chunk = [&](int chunk, int stage) {
        const char* asrc = (const char*)(g_cnb + (size_t)bm * DD + chunk * BK);
        const char* bsrc = (const char*)(g_enb + (size_t)bn * DD + chunk * BK);
        const uint32_t sa = smb + stage * STAGE;
        #pragma unroll
        for (int i = 0; i < 8; i++) {
            int idx = tid + i * 128;            // [0,1024)
            int r = idx >> 3, c = idx & 7;
            uint32_t soff = r * 128 + ((c ^ (r & 7)) * 16);
            const void* ga = asrc + (size_t)r * (DD * 2) + c * 16;
            const void* gb = bsrc + (size_t)r * (DD * 2) + c * 16;
            asm volatile("cp.async.cg.shared.global [%0], [%1], 16;"
                         :: "r"(sa + soff), "l"(ga));
            asm volatile("cp.async.cg.shared.global [%0], [%1], 16;"
                         :: "r"(sa + SBOFF + soff), "l"(gb));
        }
        asm volatile("cp.async.commit_group;" ::: "memory");
    };

    auto compute = [&](int stage) {
        const uint32_t abase = smb + stage * STAGE + (wm * 64) * 128;
        const uint32_t bbase = smb + stage * STAGE + SBOFF + (wn * 64) * 128;
        #pragma unroll
        for (int kk = 0; kk < 4; kk++) {
            const int cg = kk * 2 + (lid >> 4);
            uint32_t a[4][4];
            #pragma unroll
            for (int mi = 0; mi < 4; mi++) {
                int r = mi * 16 + (lid & 15);
                uint32_t addr = abase + r * 128 + ((cg ^ (r & 7)) * 16);
                asm volatile("ldmatrix.sync.aligned.m8n8.x4.shared.b16 {%0,%1,%2,%3}, [%4];"
                             : "=r"(a[mi][0]), "=r"(a[mi][1]), "=r"(a[mi][2]), "=r"(a[mi][3])
                             : "r"(addr));
            }
            uint32_t b[4][4];
            #pragma unroll
            for (int nb = 0; nb < 4; nb++) {
                int r = nb * 16 + (lid & 15);
                uint32_t addr = bbase + r * 128 + ((cg ^ (r & 7)) * 16);
                asm volatile("ldmatrix.sync.aligned.m8n8.x4.shared.b16 {%0,%1,%2,%3}, [%4];"
                             : "=r"(b[nb][0]), "=r"(b[nb][1]), "=r"(b[nb][2]), "=r"(b[nb][3])
                             : "r"(addr));
            }
            #pragma unroll
            for (int mi = 0; mi < 4; mi++)
                #pragma unroll
                for (int nj = 0; nj < 8; nj++) {
                    const int nb = nj >> 1, hi = nj & 1;
                    asm volatile(
                        "mma.sync.aligned.m16n8k16.row.col.f32.bf16.bf16.f32 "
                        "{%0,%1,%2,%3}, {%4,%5,%6,%7}, {%8,%9}, {%0,%1,%2,%3};"
                        : "+f"(acc[mi][nj][0]), "+f"(acc[mi][nj][1]),
                          "+f"(acc[mi][nj][2]), "+f"(acc[mi][nj][3])
                        : "r"(a[mi][0]), "r"(a[mi][1]), "r"(a[mi][2]), "r"(a[mi][3]),
                          "r"(b[nb][hi]), "r"(b[nb][2 + hi]));
                }
        }
    };

    load_chunk(0, 0);
    load_chunk(1, 1);
    #pragma unroll
    for (int k = 0; k < NCHUNKS; k++) {
        if (k < NCHUNKS - 1)
            asm volatile("cp.async.wait_group 1;" ::: "memory");
        else
            asm volatile("cp.async.wait_group 0;" ::: "memory");
        __syncthreads();
        if (k + 2 < NCHUNKS) load_chunk(k + 2, (k + 2) % 3);
        compute(k % 3);
    }

    // ---- epilogue: exp with fixed max M0 = 1/T ----
    float* sm_row = (float*)(smem + SRED);
    float* sm_col = sm_row + 128;
    __syncthreads();
    sm_row[tid] = 0.0f;
    sm_col[tid] = 0.0f;
    __syncthreads();

    const float invT = 1.0f / *tptr;
    const float M0 = invT;
    const bool hasdiag = (bm == bn);
    float rowacc[4][2] = {};
    float colacc[8][2] = {};

    #pragma unroll
    for (int mi = 0; mi < 4; mi++)
        #pragma unroll
        for (int nj = 0; nj < 8; nj++)
            #pragma unroll
            for (int e = 0; e < 4; e++) {
                const int h = e >> 1, p = e & 1;
                float logit = acc[mi][nj][e] * invT;
                float ex = __expf(logit - M0);
                if (hasdiag) {
                    int gr = wm * 64 + mi * 16 + h * 8 + (lid >> 2);
                    int gc = wn * 64 + nj * 8 + (lid & 3) * 2 + p;
                    if (gr == gc) { g_diag[bm + gr] = logit; ex = 0.0f; }
                }
                rowacc[mi][h] += ex;
                colacc[nj][p] += ex;
            }

    #pragma unroll
    for (int mi = 0; mi < 4; mi++)
        #pragma unroll
        for (int h = 0; h < 2; h++) {
            float v = rowacc[mi][h];
            v += __shfl_xor_sync(0xffffffffu, v, 1);
            v += __shfl_xor_sync(0xffffffffu, v, 2);
            if ((lid & 3) == 0)
                atomicAdd(&sm_row[wm * 64 + mi * 16 + h * 8 + (lid >> 2)], v);
        }
    #pragma unroll
    for (int nj = 0; nj < 8; nj++)
        #pragma unroll
        for (int p = 0; p < 2; p++) {
            float v = colacc[nj][p];
            v += __shfl_xor_sync(0xffffffffu, v, 4);
            v += __shfl_xor_sync(0xffffffffu, v, 8);
            v += __shfl_xor_sync(0xffffffffu, v, 16);
            if (lid < 4)
                atomicAdd(&sm_col[wn * 64 + nj * 8 + (lid & 3) * 2 + p], v);
        }
    __syncthreads();

    g_prow[(size_t)blockIdx.x * NN + bm + tid] = sm_row[tid];
    g_pcol[(size_t)blockIdx.y * NN + bn + tid] = sm_col[tid];
}

// ------------- 3. reduce partials: blocks 0-31 rows, 32-63 cols -------------
__global__ void klse(const float* __restrict__ tptr, float* __restrict__ out) {
    const float M0 = 1.0f / *tptr;
    const int isrow = blockIdx.x < 32;
    int i = (blockIdx.x & 31) * 256 + threadIdx.x;
    const float* part = isrow ? g_prow : g_pcol;
    float s = 0.0f;
    #pragma unroll 8
    for (int t = 0; t < 64; t++) s += part[(size_t)t * NN + i];
    float v = M0 + __logf(s) - g_diag[i];

    __shared__ float red[256];
    red[threadIdx.x] = v;
    __syncthreads();
    for (int o = 128; o; o >>= 1) {
        if (threadIdx.x < o) red[threadIdx.x] += red[threadIdx.x + o];
        __syncthreads();
    }
    if (threadIdx.x == 0) atomicAdd(out, red[0] * (1.0f / (float)NN));
}

// ------------- launcher ------------------------------------------------------
extern "C" void kernel_launch(void* const* d_in, const int* in_sizes, int n_in,
                              void* d_out, int out_size) {
    const float* cxr  = (const float*)d_in[0];
    const float* ehr  = (const float*)d_in[1];
    const float* temp = (const float*)d_in[2];

    __nv_bfloat16 *cnb, *enb;
    cudaGetSymbolAddress((void**)&cnb, g_cnb);
    cudaGetSymbolAddress((void**)&enb, g_enb);

    cudaFuncSetAttribute(kmain, cudaFuncAttributeMaxDynamicSharedMemorySize,
                         SMEM_TOTAL);

    knorm<<<2 * NN / 8, 256>>>(cxr, ehr, cnb, enb, (float*)d_out);
    kmain<<<dim3(GRID_X, GRID_Y), 128, SMEM_TOTAL>>>(temp);
    klse<<<64, 256>>>(temp, (float*)d_out);
}

// round 15
// speedup vs baseline: 1.1434x; 1.1434x over previous
#include <cuda_runtime.h>
#include <cuda_bf16.h>
#include <cstdint>
#include <math.h>

#define NN 8192
#define DD 512

#define BM 128
#define BN 128
#define BK 64                        // bf16 per chunk = 128 B per row
#define NCHUNKS (DD / BK)            // 8
#define GRID_X (NN / BN)             // 64
#define GRID_Y (NN / BM)             // 64

// dynamic SMEM: 3 stages x (A 16KB + B 16KB)
#define STAGE 32768
#define SBOFF 16384
#define SMEM_TOTAL 98304

__device__ __nv_bfloat16 g_cnb[(size_t)NN * DD];
__device__ __nv_bfloat16 g_enb[(size_t)NN * DD];
__device__ float g_rowsum[NN];
__device__ float g_colsum[NN];
__device__ float g_diag[NN];

__device__ __forceinline__ uint32_t smem_u32(const void* p) {
    uint32_t a;
    asm("{ .reg .u64 t; cvta.to.shared.u64 t, %1; cvt.u32.u64 %0, t; }"
        : "=r"(a) : "l"(p));
    return a;
}

// ------------- 1. normalize -> bf16: one warp per row; zero accumulators ----
__global__ void knorm(const float* __restrict__ in0, const float* __restrict__ in1,
                      __nv_bfloat16* __restrict__ out0, __nv_bfloat16* __restrict__ out1,
                      float* __restrict__ loss_out) {
    if (blockIdx.x == 0 && threadIdx.x == 0) loss_out[0] = 0.0f;
    // zero g_rowsum/g_colsum: 2048 blocks x 8 elems = 16384 = 2*NN
    if (threadIdx.x < 8) {
        int i = blockIdx.x * 8 + threadIdx.x;
        if (i < NN) g_rowsum[i] = 0.0f;
        else        g_colsum[i - NN] = 0.0f;
    }
    const int wid = threadIdx.x >> 5, lid = threadIdx.x & 31;
    int gr = blockIdx.x * 8 + wid;                   // [0, 2*NN)
    const float* in = (gr < NN) ? in0 : in1;
    __nv_bfloat16* out = (gr < NN) ? out0 : out1;
    int row = gr & (NN - 1);

    const float4* ip = reinterpret_cast<const float4*>(in + (size_t)row * DD);
    float4 v[4];
    #pragma unroll
    for (int j = 0; j < 4; j++) v[j] = ip[lid + 32 * j];

    float ss = 0.0f;
    #pragma unroll
    for (int j = 0; j < 4; j++)
        ss += v[j].x * v[j].x + v[j].y * v[j].y + v[j].z * v[j].z + v[j].w * v[j].w;
    #pragma unroll
    for (int o = 16; o; o >>= 1) ss += __shfl_xor_sync(0xffffffffu, ss, o);
    float inv = 1.0f / fmaxf(sqrtf(ss), 1e-8f);

    uint2* op = reinterpret_cast<uint2*>(out + (size_t)row * DD);
    #pragma unroll
    for (int j = 0; j < 4; j++) {
        __nv_bfloat162 lo = __floats2bfloat162_rn(v[j].x * inv, v[j].y * inv);
        __nv_bfloat162 hi = __floats2bfloat162_rn(v[j].z * inv, v[j].w * inv);
        uint2 w;
        w.x = *reinterpret_cast<uint32_t*>(&lo);
        w.y = *reinterpret_cast<uint32_t*>(&hi);
        op[lid + 32 * j] = w;
    }
}

// ------------- 2. fused bf16 mma.sync GEMM + exp-sum epilogue (R12 loop) ----
// 8 warps: warp grid 4(M) x 2(N); warp tile 32x64
// 3-stage cp.async pipeline, fully unrolled, 1 barrier per chunk
__global__ void __launch_bounds__(256, 2) kmain(const float* __restrict__ tptr) {
    extern __shared__ char smem[];
    const uint32_t smb = smem_u32(smem);
    const int tid = threadIdx.x;
    const int wid = tid >> 5, lid = tid & 31;
    const int wm = wid >> 1, wn = wid & 1;
    const int bm = blockIdx.y * BM;
    const int bn = blockIdx.x * BN;

    float acc[2][8][4];
    #pragma unroll
    for (int i = 0; i < 2; i++)
        #pragma unroll
        for (int j = 0; j < 8; j++)
            #pragma unroll
            for (int e = 0; e < 4; e++) acc[i][j][e] = 0.0f;

    auto load_chunk = [&](int chunk, int stage) {
        const char* asrc = (const char*)(g_cnb + (size_t)bm * DD + chunk * BK);
        const char* bsrc = (const char*)(g_enb + (size_t)bn * DD + chunk * BK);
        const uint32_t sa = smb + stage * STAGE;
        #pragma unroll
        for (int i = 0; i < 4; i++) {
            int idx = tid + i * 256;            // [0,1024)
            int r = idx >> 3, c = idx & 7;
            uint32_t soff = r * 128 + ((c ^ (r & 7)) * 16);
            const void* ga = asrc + (size_t)r * (DD * 2) + c * 16;
            const void* gb = bsrc + (size_t)r * (DD * 2) + c * 16;
            asm volatile("cp.async.cg.shared.global [%0], [%1], 16;"
                         :: "r"(sa + soff), "l"(ga));
            asm volatile("cp.async.cg.shared.global [%0], [%1], 16;"
                         :: "r"(sa + SBOFF + soff), "l"(gb));
        }
        asm volatile("cp.async.commit_group;" ::: "memory");
    };

    auto compute = [&](int stage) {
        const uint32_t abase = smb + stage * STAGE + (wm * 32) * 128;
        const uint32_t bbase = smb + stage * STAGE + SBOFF + (wn * 64) * 128;
        #pragma unroll
        for (int kk = 0; kk < 4; kk++) {
            const int cg = kk * 2 + (lid >> 4);
            uint32_t a[2][4];
            #pragma unroll
            for (int mi = 0; mi < 2; mi++) {
                int r = mi * 16 + (lid & 15);
                uint32_t addr = abase + r * 128 + ((cg ^ (r & 7)) * 16);
                asm volatile("ldmatrix.sync.aligned.m8n8.x4.shared.b16 {%0,%1,%2,%3}, [%4];"
                             : "=r"(a[mi][0]), "=r"(a[mi][1]), "=r"(a[mi][2]), "=r"(a[mi][3])
                             : "r"(addr));
            }
            uint32_t b[4][4];
            #pragma unroll
            for (int nb = 0; nb < 4; nb++) {
                int r = nb * 16 + (lid & 15);
                uint32_t addr = bbase + r * 128 + ((cg ^ (r & 7)) * 16);
                asm volatile("ldmatrix.sync.aligned.m8n8.x4.shared.b16 {%0,%1,%2,%3}, [%4];"
                             : "=r"(b[nb][0]), "=r"(b[nb][1]), "=r"(b[nb][2]), "=r"(b[nb][3])
                             : "r"(addr));
            }
            #pragma unroll
            for (int mi = 0; mi < 2; mi++)
                #pragma unroll
                for (int nj = 0; nj < 8; nj++) {
                    const int nb = nj >> 1, hi = nj & 1;
                    asm volatile(
                        "mma.sync.aligned.m16n8k16.row.col.f32.bf16.bf16.f32 "
                        "{%0,%1,%2,%3}, {%4,%5,%6,%7}, {%8,%9}, {%0,%1,%2,%3};"
                        : "+f"(acc[mi][nj][0]), "+f"(acc[mi][nj][1]),
                          "+f"(acc[mi][nj][2]), "+f"(acc[mi][nj][3])
                        : "r"(a[mi][0]), "r"(a[mi][1]), "r"(a[mi][2]), "r"(a[mi][3]),
                          "r"(b[nb][hi]), "r"(b[nb][2 + hi]));
                }
        }
    };

    load_chunk(0, 0);
    load_chunk(1, 1);
    #pragma unroll
    for (int k = 0; k < NCHUNKS; k++) {
        if (k < NCHUNKS - 1)
            asm volatile("cp.async.wait_group 1;" ::: "memory");
        else
            asm volatile("cp.async.wait_group 0;" ::: "memory");
        __syncthreads();
        if (k + 2 < NCHUNKS) load_chunk(k + 2, (k + 2) % 3);
        compute(k % 3);
    }

    // ---- epilogue: exp (fixed shift M0 = 1/T), direct global atomics ----
    const float invT = 1.0f / *tptr;
    const float M0 = invT;
    const bool hasdiag = (bm == bn);
    float rowacc[2][2] = {};
    float colacc[8][2] = {};

    #pragma unroll
    for (int mi = 0; mi < 2; mi++)
        #pragma unroll
        for (int nj = 0; nj < 8; nj++)
            #pragma unroll
            for (int e = 0; e < 4; e++) {
                const int h = e >> 1, p = e & 1;
                float logit = acc[mi][nj][e] * invT;
                float ex = __expf(logit - M0);
                if (hasdiag) {
                    int gr = wm * 32 + mi * 16 + h * 8 + (lid >> 2);
                    int gc = wn * 64 + nj * 8 + (lid & 3) * 2 + p;
                    if (gr == gc) { g_diag[bm + gr] = logit; ex = 0.0f; }
                }
                rowacc[mi][h] += ex;
                colacc[nj][p] += ex;
            }

    #pragma unroll
    for (int mi = 0; mi < 2; mi++)
        #pragma unroll
        for (int h = 0; h < 2; h++) {
            float v = rowacc[mi][h];
            v += __shfl_xor_sync(0xffffffffu, v, 1);
            v += __shfl_xor_sync(0xffffffffu, v, 2);
            if ((lid & 3) == 0)
                atomicAdd(&g_rowsum[bm + wm * 32 + mi * 16 + h * 8 + (lid >> 2)], v);
        }
    #pragma unroll
    for (int nj = 0; nj < 8; nj++)
        #pragma unroll
        for (int p = 0; p < 2; p++) {
            float v = colacc[nj][p];
            v += __shfl_xor_sync(0xffffffffu, v, 4);
            v += __shfl_xor_sync(0xffffffffu, v, 8);
            v += __shfl_xor_sync(0xffffffffu, v, 16);
            if (lid < 4)
                atomicAdd(&g_colsum[bn + wn * 64 + nj * 8 + (lid & 3) * 2 + p], v);
        }
}

// ------------- 3. combine sums -> LSEs -> loss ------------------------------
__global__ void klse(const float* __restrict__ tptr, float* __restrict__ out) {
    const float M0 = 1.0f / *tptr;
    int i = blockIdx.x * 256 + threadIdx.x;
    float v = 2.0f * M0 + __logf(g_rowsum[i]) + __logf(g_colsum[i])
            - 2.0f * g_diag[i];

    __shared__ float red[256];
    red[threadIdx.x] = v;
    __syncthreads();
    for (int o = 128; o; o >>= 1) {
        if (threadIdx.x < o) red[threadIdx.x] += red[threadIdx.x + o];
        __syncthreads();
    }
    if (threadIdx.x == 0) atomicAdd(out, red[0] * (1.0f / (float)NN));
}

// ------------- launcher ------------------------------------------------------
extern "C" void kernel_launch(void* const* d_in, const int* in_sizes, int n_in,
                              void* d_out, int out_size) {
    const float* cxr  = (const float*)d_in[0];
    const float* ehr  = (const float*)d_in[1];
    const float* temp = (const float*)d_in[2];

    __nv_bfloat16 *cnb, *enb;
    cudaGetSymbolAddress((void**)&cnb, g_cnb);
    cudaGetSymbolAddress((void**)&enb, g_enb);

    cudaFuncSetAttribute(kmain, cudaFuncAttributeMaxDynamicSharedMemorySize,
                         SMEM_TOTAL);

    knorm<<<2 * NN / 8, 256>>>(cxr, ehr, cnb, enb, (float*)d_out);
    kmain<<<dim3(GRID_X, GRID_Y), 256, SMEM_TOTAL>>>(temp);
    klse<<<NN / 256, 256>>>(temp, (float*)d_out);
}